// round 8
// baseline (speedup 1.0000x reference)
#include <cuda_runtime.h>
#include <cuda_bf16.h>
#include <math.h>
#include <stdint.h>

typedef unsigned long long ull;

// ---------------------------------------------------------------------------
// PSA quaternion block on GB300 (compiled via compute_103 -> legacy mma.sync).
//   activations: [B=4, C, 4, HW=1024] fp32 -> per-batch row-major (C*4) x 1024
//   quaternion weights: [4, Cout, Cin, kh, kw]
// 1x1 qconvs as real GEMMs on HMMA (bf16 mma.sync, 3-term split-bf16 for
// fp32-grade accuracy), Hamilton product folded into the A-tile loader.
// ---------------------------------------------------------------------------

__constant__ int   c_WIDX[16] = {0,1,2,3,  1,0,3,2,  2,3,0,1,  3,2,1,0};
__constant__ float c_SGN [16] = {1,-1,-1,-1,  1,1,1,-1,  1,-1,1,1,  1,1,-1,1};

// ------------------------------ scratch ------------------------------------
__device__ float g_h1 [4*512*1024];
__device__ float g_qkv[4*768*1024];
__device__ float g_o  [4*256*1024];
__device__ float g_o2 [4*256*1024];
__device__ float g_p  [4*256*1024];
__device__ float g_f1 [4*512*1024];
__device__ float g_cat[4*512*1024];

// --------------------------- helpers ---------------------------------------
__device__ __forceinline__ uint32_t smem_u32(const void* p) {
    uint32_t a;
    asm("{ .reg .u64 t; cvta.to.shared.u64 t, %1; cvt.u32.u64 %0, t; }"
        : "=r"(a) : "l"(p));
    return a;
}
__device__ __forceinline__ uint16_t bfbits(float x) {
    __nv_bfloat16 b = __float2bfloat16(x);
    return *(uint16_t*)&b;
}
__device__ __forceinline__ float bf2f(uint16_t u) {
    __nv_bfloat16 b = *(__nv_bfloat16*)&u;
    return __bfloat162float(b);
}

__device__ __forceinline__ void ldm_x4(uint32_t* r, uint32_t addr) {
    asm volatile("ldmatrix.sync.aligned.m8n8.x4.shared.b16 {%0,%1,%2,%3}, [%4];"
                 : "=r"(r[0]), "=r"(r[1]), "=r"(r[2]), "=r"(r[3]) : "r"(addr));
}
__device__ __forceinline__ void mma_bf16(float* c, const uint32_t* a,
                                         uint32_t b0, uint32_t b1) {
    asm volatile(
        "mma.sync.aligned.m16n8k16.row.col.f32.bf16.bf16.f32 "
        "{%0,%1,%2,%3}, {%4,%5,%6,%7}, {%8,%9}, {%0,%1,%2,%3};"
        : "+f"(c[0]), "+f"(c[1]), "+f"(c[2]), "+f"(c[3])
        : "r"(a[0]), "r"(a[1]), "r"(a[2]), "r"(a[3]), "r"(b0), "r"(b1));
}

// f32x2 packed math (attention)
__device__ __forceinline__ ull fma2(ull a, ull b, ull c) {
    ull d; asm("fma.rn.f32x2 %0, %1, %2, %3;" : "=l"(d) : "l"(a), "l"(b), "l"(c));
    return d;
}
__device__ __forceinline__ ull mul2(ull a, ull b) {
    ull d; asm("mul.rn.f32x2 %0, %1, %2;" : "=l"(d) : "l"(a), "l"(b));
    return d;
}
__device__ __forceinline__ ull pk2(float lo, float hi) {
    ull r; asm("mov.b64 %0, {%1, %2};" : "=l"(r) : "f"(lo), "f"(hi));
    return r;
}
__device__ __forceinline__ float2 upk2(ull a) {
    float lo, hi; asm("mov.b64 {%0, %1}, %2;" : "=f"(lo), "=f"(hi) : "l"(a));
    return make_float2(lo, hi);
}

// ------------------------- mma.sync bf16 GEMM ------------------------------
// Y_b[M x 1024] = Weff[M x K] * X_b[K x 1024] (+bias), M=Cout*4, K=Cin*4.
// CTA tile 128(M) x 128(N), 8 warps (4m x 2n), warp tile 32x64, BK=32.
// smem rows padded to 80B (conflict-free ldmatrix). Double-buffered.
//   per buffer 40960B: A_hi(10240) A_lo(10240) B_hi(10240) B_lo(10240)
#define ROWB   80u
#define BUF_SZ 40960u
#define GEMM_SMEM (2 * 40960)

__device__ __forceinline__ void stage_load(char* sm, uint32_t boff,
    const float* __restrict__ w, int Cout, int Cin,
    const float* __restrict__ Xb, int m0, int n0, int k0, int tid)
{
    // ---- A tile: 128 rows(m) x 32 cols(k), Hamilton expansion + bf16 split
    {
        int m  = tid & 127;
        int kb = (tid >> 7) << 4;               // 0 or 16
        int mg = m0 + m;
        int oc = mg >> 2, co = mg & 3;
        uint16_t hh[16], ll[16];
#pragma unroll
        for (int j = 0; j < 16; j++) {
            int kg = k0 + kb + j;
            int ic = kg >> 2, ci = kg & 3;
            int e = co * 4 + ci;
            float val = c_SGN[e] * w[((size_t)c_WIDX[e] * Cout + oc) * Cin + ic];
            uint16_t h = bfbits(val);
            hh[j] = h;
            ll[j] = bfbits(val - bf2f(h));
        }
        char* pa = sm + boff + (uint32_t)m * ROWB + (uint32_t)(kb << 1);
        *(uint4*)(pa)               = *(uint4*)&hh[0];
        *(uint4*)(pa + 16)          = *(uint4*)&hh[8];
        *(uint4*)(pa + 10240)       = *(uint4*)&ll[0];
        *(uint4*)(pa + 10240 + 16)  = *(uint4*)&ll[8];
    }
    // ---- B tile: Bs[n][k] = X[k0+k][n0+n], 128 n x 32 k, bf16 split
    {
        int n8 = (tid >> 4) << 3;               // 0..120
        int k2 = (tid & 15) << 1;               // 0..30
        const float* x0 = Xb + (size_t)(k0 + k2) * 1024 + n0 + n8;
        const float* x1 = x0 + 1024;
        float va[8], vb[8];
        *(float4*)&va[0] = *(const float4*)x0;
        *(float4*)&va[4] = *(const float4*)(x0 + 4);
        *(float4*)&vb[0] = *(const float4*)x1;
        *(float4*)&vb[4] = *(const float4*)(x1 + 4);
        char* pb = sm + boff + 20480 + (uint32_t)(k2 << 1);
#pragma unroll
        for (int i = 0; i < 8; i++) {
            uint16_t ha = bfbits(va[i]);
            uint16_t hb = bfbits(vb[i]);
            uint16_t la = bfbits(va[i] - bf2f(ha));
            uint16_t lb = bfbits(vb[i] - bf2f(hb));
            uint32_t ph = (uint32_t)ha | ((uint32_t)hb << 16);
            uint32_t pl = (uint32_t)la | ((uint32_t)lb << 16);
            char* r = pb + (uint32_t)(n8 + i) * ROWB;
            *(uint32_t*)(r)         = ph;
            *(uint32_t*)(r + 10240) = pl;
        }
    }
}

__global__ __launch_bounds__(256) void hgemm(
    const float* __restrict__ w, const float* __restrict__ X,
    float* __restrict__ Y, const float* __restrict__ bias,
    int Cout, int Cin, int NS, int in_bs, int out_bs)
{
    extern __shared__ char sm[];
    const int tid  = threadIdx.x;
    const int b    = blockIdx.z;
    const int m0   = blockIdx.y * 128;
    const int n0   = blockIdx.x * 128;
    const float* Xb = X + (size_t)b * in_bs;
    float* Yb = Y + (size_t)b * out_bs;
    const uint32_t smb = smem_u32(sm);

    const int lane = tid & 31;
    const int wrp  = tid >> 5;
    const int wm   = (wrp & 3) << 5;            // 0,32,64,96
    const int wn   = (wrp >> 2) << 6;           // 0,64

    float acc[2][8][4];
#pragma unroll
    for (int i = 0; i < 2; i++)
#pragma unroll
        for (int j = 0; j < 8; j++)
#pragma unroll
            for (int q = 0; q < 4; q++) acc[i][j][q] = 0.f;

    // precomputed ldmatrix lane address offsets
    const int a_row = (lane & 15);
    const int a_kc  = (lane >> 4) << 3;
    const int b_row = (lane & 7) + ((lane >> 4) << 3);
    const int b_kc  = ((lane >> 3) & 1) << 3;

    stage_load(sm, 0, w, Cout, Cin, Xb, m0, n0, 0, tid);
    __syncthreads();

    for (int s = 0; s < NS; s++) {
        if (s + 1 < NS)
            stage_load(sm, (uint32_t)((s + 1) & 1) * BUF_SZ,
                       w, Cout, Cin, Xb, m0, n0, (s + 1) * 32, tid);

        uint32_t base = smb + (uint32_t)(s & 1) * BUF_SZ;
        uint32_t Ah = base, Al = base + 10240;
        uint32_t Bh = base + 20480, Bl = base + 30720;

#pragma unroll
        for (int kk = 0; kk < 32; kk += 16) {
            uint32_t ah[2][4], al[2][4];
#pragma unroll
            for (int mt = 0; mt < 2; mt++) {
                uint32_t off = (uint32_t)(wm + mt * 16 + a_row) * ROWB +
                               (uint32_t)((kk + a_kc) << 1);
                ldm_x4(ah[mt], Ah + off);
                ldm_x4(al[mt], Al + off);
            }
#pragma unroll
            for (int gt = 0; gt < 4; gt++) {
                uint32_t off = (uint32_t)(wn + gt * 16 + b_row) * ROWB +
                               (uint32_t)((kk + b_kc) << 1);
                uint32_t bh[4], bl[4];
                ldm_x4(bh, Bh + off);
                ldm_x4(bl, Bl + off);
#pragma unroll
                for (int mt = 0; mt < 2; mt++) {
#pragma unroll
                    for (int h = 0; h < 2; h++) {
                        float* c = acc[mt][gt * 2 + h];
                        mma_bf16(c, ah[mt], bh[2 * h], bh[2 * h + 1]);
                        mma_bf16(c, ah[mt], bl[2 * h], bl[2 * h + 1]);
                        mma_bf16(c, al[mt], bh[2 * h], bh[2 * h + 1]);
                    }
                }
            }
        }
        __syncthreads();
    }

    // epilogue: fragment (row=lane/4 & +8, col=2*(lane%4)+{0,1})
#pragma unroll
    for (int mt = 0; mt < 2; mt++) {
        int r0 = m0 + wm + mt * 16 + (lane >> 2);
        int r1 = r0 + 8;
        float bv0 = bias ? bias[r0] : 0.f;
        float bv1 = bias ? bias[r1] : 0.f;
        float* y0 = Yb + (size_t)r0 * 1024;
        float* y1 = Yb + (size_t)r1 * 1024;
#pragma unroll
        for (int nt = 0; nt < 8; nt++) {
            int col = n0 + wn + nt * 8 + ((lane & 3) << 1);
            float* c = acc[mt][nt];
            *(float2*)(y0 + col) = make_float2(c[0] + bv0, c[1] + bv0);
            *(float2*)(y1 + col) = make_float2(c[2] + bv1, c[3] + bv1);
        }
    }
}

// ------------------------------- IQBN --------------------------------------
__global__ __launch_bounds__(256) void iqbn_kernel(
    const float* __restrict__ x, float* __restrict__ y,
    const float* __restrict__ gam, const float* __restrict__ bet,
    int in_bs, int out_bs, int do_relu)
{
    int c4 = blockIdx.x;
    int tid = threadIdx.x;
    float v[16];
    float s = 0.f, ss = 0.f;
#pragma unroll
    for (int i = 0; i < 16; i++) {
        int e = tid + (i << 8);
        int bb = e >> 10, hw = e & 1023;
        float t = x[(size_t)bb * in_bs + (size_t)c4 * 1024 + hw];
        v[i] = t; s += t; ss += t * t;
    }
    __shared__ float rs[256], rq[256];
    rs[tid] = s; rq[tid] = ss;
    __syncthreads();
    for (int o = 128; o > 0; o >>= 1) {
        if (tid < o) { rs[tid] += rs[tid + o]; rq[tid] += rq[tid + o]; }
        __syncthreads();
    }
    float mean = rs[0] * (1.0f / 4096.0f);
    float var  = rq[0] * (1.0f / 4096.0f) - mean * mean;
    float rstd = rsqrtf(var + 1e-5f);
    float gg = gam[c4] * rstd;
    float bb2 = bet[c4] - mean * gg;
#pragma unroll
    for (int i = 0; i < 16; i++) {
        int e = tid + (i << 8);
        int bb = e >> 10, hw = e & 1023;
        float t = v[i] * gg + bb2;
        if (do_relu) t = fmaxf(t, 0.f);
        y[(size_t)bb * out_bs + (size_t)c4 * 1024 + hw] = t;
    }
}

// ----------------------------- attention -----------------------------------
__global__ __launch_bounds__(512) void attn_kernel(const float* __restrict__ qkv,
                                                   float* __restrict__ o)
{
    extern __shared__ float smf[];
    float* Ks = smf;
    float* Vs = smf + 16 * 1024;
    int combo = blockIdx.x;
    int qc = combo & 3;
    int hh = (combo >> 2) & 3;
    int bb = combo >> 4;
    int tid = threadIdx.x;
    const size_t cs = 4 * 1024;
    const float* qb = qkv + (((size_t)bb * 192 + hh * 48 +  0) * 4 + qc) * 1024;
    const float* kb = qkv + (((size_t)bb * 192 + hh * 48 + 16) * 4 + qc) * 1024;
    const float* vb = qkv + (((size_t)bb * 192 + hh * 48 + 32) * 4 + qc) * 1024;

    for (int i = tid; i < 16 * 1024; i += 512) {
        int d = i >> 10, m = i & 1023;
        Ks[i] = kb[d * cs + m];
        Vs[i] = vb[d * cs + m];
    }
    __syncthreads();

    int n = blockIdx.y * 512 + tid;
    ull qp[16];
#pragma unroll
    for (int d = 0; d < 16; d++) {
        float qd = qb[d * cs + n] * 0.25f;
        qp[d] = pk2(qd, qd);
    }

    float mmax = -1e30f, l = 0.f;
    ull acc2[16];
#pragma unroll
    for (int d = 0; d < 16; d++) acc2[d] = 0ull;

    for (int mv = 0; mv < 256; mv++) {
        ull s01 = 0ull, s23 = 0ull;
#pragma unroll
        for (int d = 0; d < 16; d++) {
            ulonglong2 kv = *(const ulonglong2*)&Ks[d * 1024 + mv * 4];
            s01 = fma2(qp[d], kv.x, s01);
            s23 = fma2(qp[d], kv.y, s23);
        }
        float2 sA = upk2(s01), sB = upk2(s23);
        float tmax = fmaxf(fmaxf(sA.x, sA.y), fmaxf(sB.x, sB.y));
        float nm = fmaxf(mmax, tmax);
        float corr = __expf(mmax - nm);
        float p0 = __expf(sA.x - nm);
        float p1 = __expf(sA.y - nm);
        float p2 = __expf(sB.x - nm);
        float p3 = __expf(sB.y - nm);
        l = l * corr + (p0 + p1 + p2 + p3);
        ull p01 = pk2(p0, p1), p23 = pk2(p2, p3), c2 = pk2(corr, corr);
#pragma unroll
        for (int d = 0; d < 16; d++) {
            ulonglong2 vv = *(const ulonglong2*)&Vs[d * 1024 + mv * 4];
            ull t = mul2(p01, vv.x);
            t = fma2(p23, vv.y, t);
            acc2[d] = fma2(acc2[d], c2, t);
        }
        mmax = nm;
    }
    float inv = 1.f / l;
#pragma unroll
    for (int d = 0; d < 16; d++) {
        float2 a = upk2(acc2[d]);
        o[(((size_t)bb * 64 + hh * 16 + d) * 4 + qc) * 1024 + n] = (a.x + a.y) * inv;
    }
}

// --------------------- 3x3 grouped quaternion PE conv ----------------------
__global__ __launch_bounds__(1024) void pe_kernel(
    const float* __restrict__ o, const float* __restrict__ pw,
    const float* __restrict__ pb, float* __restrict__ o2)
{
    int blk = blockIdx.x;
    int co = blk & 3;
    int oc = (blk >> 2) & 63;
    int bb = blk >> 8;
    int t = threadIdx.x;
    int y = t >> 5, xq = t & 31;
    int g = oc >> 2;

    float acc = pb[oc * 4 + co];
#pragma unroll
    for (int ci = 0; ci < 4; ci++) {
        int wc  = c_WIDX[co * 4 + ci];
        float s = c_SGN [co * 4 + ci];
#pragma unroll
        for (int ic = 0; ic < 4; ic++) {
            const float* xp = o  + (((size_t)bb * 64 + g * 4 + ic) * 4 + ci) * 1024;
            const float* wp = pw + (((size_t)wc * 64 + oc) * 4 + ic) * 9;
            float sum = 0.f;
#pragma unroll
            for (int ky = 0; ky < 3; ky++) {
                int yy = y + ky - 1;
                if (yy < 0 || yy > 31) continue;
#pragma unroll
                for (int kx = 0; kx < 3; kx++) {
                    int xx = xq + kx - 1;
                    if (xx < 0 || xx > 31) continue;
                    sum += xp[yy * 32 + xx] * wp[ky * 3 + kx];
                }
            }
            acc += s * sum;
        }
    }
    size_t oi = (((size_t)bb * 64 + oc) * 4 + co) * 1024 + t;
    o2[oi] = o[oi] + acc;
}

// ---------------------- copy b-branch into concat --------------------------
__global__ void copy_b_kernel(const float* __restrict__ h1, float* __restrict__ cat)
{
    int i = blockIdx.x * blockDim.x + threadIdx.x;
    int hw = i & 1023;
    int c4 = (i >> 10) & 255;
    int bb = i >> 18;
    size_t off = ((size_t)bb * 512 + 256 + c4) * 1024 + hw;
    cat[off] = h1[off];
}

// ---------------------------------------------------------------------------
extern "C" void kernel_launch(void* const* d_in, const int* in_sizes, int n_in,
                              void* d_out, int out_size)
{
    const float* x      = (const float*)d_in[0];
    const float* cv1_w  = (const float*)d_in[1];
    const float* bn1_g  = (const float*)d_in[2];
    const float* bn1_b  = (const float*)d_in[3];
    const float* qkv_w  = (const float*)d_in[4];
    const float* qkv_b  = (const float*)d_in[5];
    const float* proj_w = (const float*)d_in[6];
    const float* proj_b = (const float*)d_in[7];
    const float* pe_w   = (const float*)d_in[8];
    const float* pe_b   = (const float*)d_in[9];
    const float* an_g   = (const float*)d_in[10];
    const float* an_b   = (const float*)d_in[11];
    const float* ffn1_w = (const float*)d_in[12];
    const float* fbn1_g = (const float*)d_in[13];
    const float* fbn1_b = (const float*)d_in[14];
    const float* ffn2_w = (const float*)d_in[15];
    const float* fbn2_g = (const float*)d_in[16];
    const float* fbn2_b = (const float*)d_in[17];
    const float* cv2_w  = (const float*)d_in[18];
    const float* bn2_g  = (const float*)d_in[19];
    const float* bn2_b  = (const float*)d_in[20];
    float* out = (float*)d_out;

    float *h1, *qkv, *o, *o2, *p, *f1, *cat;
    cudaGetSymbolAddress((void**)&h1,  g_h1);
    cudaGetSymbolAddress((void**)&qkv, g_qkv);
    cudaGetSymbolAddress((void**)&o,   g_o);
    cudaGetSymbolAddress((void**)&o2,  g_o2);
    cudaGetSymbolAddress((void**)&p,   g_p);
    cudaGetSymbolAddress((void**)&f1,  g_f1);
    cudaGetSymbolAddress((void**)&cat, g_cat);

    cudaFuncSetAttribute(hgemm, cudaFuncAttributeMaxDynamicSharedMemorySize,
                         GEMM_SMEM);
    cudaFuncSetAttribute(attn_kernel, cudaFuncAttributeMaxDynamicSharedMemorySize,
                         131072);

    const int BS512 = 512 * 1024;
    const int BS768 = 768 * 1024;
    const int BS256 = 256 * 1024;

    // 1) cv1 + bn1 + relu -> h1
    hgemm<<<dim3(8, 4, 4), 256, GEMM_SMEM>>>(cv1_w, x, h1, nullptr,
                                             128, 128, 16, BS512, BS512);
    iqbn_kernel<<<512, 256>>>(h1, h1, bn1_g, bn1_b, BS512, BS512, 1);

    // 2) qkv (a-branch = h1 rows 0..255)
    hgemm<<<dim3(8, 6, 4), 256, GEMM_SMEM>>>(qkv_w, h1, qkv, qkv_b,
                                             192, 64, 8, BS512, BS768);

    // 3) attention -> o
    attn_kernel<<<dim3(64, 2), 512, 131072>>>(qkv, o);

    // 4) o2 = o + pe(o) + pe_b
    pe_kernel<<<1024, 1024>>>(o, pe_w, pe_b, o2);

    // 5) proj + attn_norm
    hgemm<<<dim3(8, 2, 4), 256, GEMM_SMEM>>>(proj_w, o2, p, proj_b,
                                             64, 64, 8, BS256, BS256);
    iqbn_kernel<<<256, 256>>>(p, p, an_g, an_b, BS256, BS256, 0);

    // 6) ffn1 + bn + relu
    hgemm<<<dim3(8, 4, 4), 256, GEMM_SMEM>>>(ffn1_w, p, f1, nullptr,
                                             128, 64, 8, BS256, BS512);
    iqbn_kernel<<<512, 256>>>(f1, f1, fbn1_g, fbn1_b, BS512, BS512, 1);

    // 7) ffn2 -> o, bn -> cat rows 0..255
    hgemm<<<dim3(8, 2, 4), 256, GEMM_SMEM>>>(ffn2_w, f1, o, nullptr,
                                             64, 128, 16, BS512, BS256);
    iqbn_kernel<<<256, 256>>>(o, cat, fbn2_g, fbn2_b, BS256, BS512, 0);

    // 8) concat b-branch
    copy_b_kernel<<<4096, 256>>>(h1, cat);

    // 9) cv2 + bn2 + relu -> out
    hgemm<<<dim3(8, 4, 4), 256, GEMM_SMEM>>>(cv2_w, cat, f1, nullptr,
                                             128, 128, 16, BS512, BS512);
    iqbn_kernel<<<512, 256>>>(f1, out, bn2_g, bn2_b, BS512, BS512, 1);
}

// round 11
// speedup vs baseline: 1.5001x; 1.5001x over previous
#include <cuda_runtime.h>
#include <cuda_bf16.h>
#include <math.h>
#include <stdint.h>

typedef unsigned long long ull;

// ---------------------------------------------------------------------------
// PSA quaternion block. activations [B=4, C, 4, 1024] fp32 = per-batch
// row-major (C*4) x 1024. 1x1 qconvs -> bf16 split HMMA GEMMs with all
// conversion hoisted into prep kernels; staging via cp.async.
// ---------------------------------------------------------------------------

__constant__ int   c_WIDX[16] = {0,1,2,3,  1,0,3,2,  2,3,0,1,  3,2,1,0};
__constant__ float c_SGN [16] = {1,-1,-1,-1,  1,1,1,-1,  1,-1,1,1,  1,1,-1,1};

// ------------------------------ scratch ------------------------------------
__device__ float g_h1 [4*512*1024];
__device__ float g_qkv[4*768*1024];
__device__ float g_o  [4*256*1024];
__device__ float g_o2 [4*256*1024];
__device__ float g_p  [4*256*1024];
__device__ float g_f1 [4*512*1024];
__device__ float g_cat[4*512*1024];
__device__ __nv_bfloat16 g_wh[512*512];
__device__ __nv_bfloat16 g_wl[512*512];
__device__ __nv_bfloat16 g_xh[4*1024*512];
__device__ __nv_bfloat16 g_xl[4*1024*512];

// --------------------------- helpers ---------------------------------------
__device__ __forceinline__ uint32_t smem_u32(const void* p) {
    uint32_t a;
    asm("{ .reg .u64 t; cvta.to.shared.u64 t, %1; cvt.u32.u64 %0, t; }"
        : "=r"(a) : "l"(p));
    return a;
}
__device__ __forceinline__ void ldm_x4(uint32_t* r, uint32_t addr) {
    asm volatile("ldmatrix.sync.aligned.m8n8.x4.shared.b16 {%0,%1,%2,%3}, [%4];"
                 : "=r"(r[0]), "=r"(r[1]), "=r"(r[2]), "=r"(r[3]) : "r"(addr));
}
__device__ __forceinline__ void mma_bf16(float* c, const uint32_t* a,
                                         uint32_t b0, uint32_t b1) {
    asm volatile(
        "mma.sync.aligned.m16n8k16.row.col.f32.bf16.bf16.f32 "
        "{%0,%1,%2,%3}, {%4,%5,%6,%7}, {%8,%9}, {%0,%1,%2,%3};"
        : "+f"(c[0]), "+f"(c[1]), "+f"(c[2]), "+f"(c[3])
        : "r"(a[0]), "r"(a[1]), "r"(a[2]), "r"(a[3]), "r"(b0), "r"(b1));
}
__device__ __forceinline__ void cpa16(uint32_t sa, const void* g) {
    asm volatile("cp.async.ca.shared.global [%0], [%1], 16;"
                 :: "r"(sa), "l"(g) : "memory");
}
#define CPA_COMMIT() asm volatile("cp.async.commit_group;" ::: "memory")
#define CPA_WAIT(n)  asm volatile("cp.async.wait_group %0;" :: "n"(n) : "memory")

// f32x2 packed math (attention)
__device__ __forceinline__ ull fma2(ull a, ull b, ull c) {
    ull d; asm("fma.rn.f32x2 %0, %1, %2, %3;" : "=l"(d) : "l"(a), "l"(b), "l"(c));
    return d;
}
__device__ __forceinline__ ull pk2(float lo, float hi) {
    ull r; asm("mov.b64 %0, {%1, %2};" : "=l"(r) : "f"(lo), "f"(hi));
    return r;
}
__device__ __forceinline__ float2 upk2(ull a) {
    float lo, hi; asm("mov.b64 {%0, %1}, %2;" : "=f"(lo), "=f"(hi) : "l"(a));
    return make_float2(lo, hi);
}
// FMA-pipe exp (no MUFU): exp(s) = 2^(s*log2e), poly on fma pipe
__device__ __forceinline__ float fexp(float s) {
    float y = s * 1.4426950408889634f;
    y = fminf(fmaxf(y, -80.f), 80.f);
    float r = rintf(y);
    float f = y - r;
    float p = 1.3333558e-3f;                 // ln2^5/120
    p = fmaf(p, f, 9.6181291e-3f);           // ln2^4/24
    p = fmaf(p, f, 5.5504109e-2f);           // ln2^3/6
    p = fmaf(p, f, 2.4022651e-1f);           // ln2^2/2
    p = fmaf(p, f, 6.9314718e-1f);           // ln2
    p = fmaf(p, f, 1.0f);
    int ib = (int)r;
    return __int_as_float(__float_as_int(p) + (ib << 23));
}

// ------------------------- prep kernels ------------------------------------
// Hamilton expand + bf16 split: w[4,Cout,Cin] -> Whi/Wlo [M=Cout*4][K=Cin*4]
__global__ void prep_w(const float* __restrict__ w,
                       __nv_bfloat16* __restrict__ wh,
                       __nv_bfloat16* __restrict__ wl, int Cout, int Cin)
{
    int idx = blockIdx.x * blockDim.x + threadIdx.x;
    int K = Cin * 4;
    if (idx >= Cout * 4 * K) return;
    int k = idx % K, m = idx / K;
    int oc = m >> 2, co = m & 3;
    int ic = k >> 2, ci = k & 3;
    int e = co * 4 + ci;
    float v = c_SGN[e] * w[((size_t)c_WIDX[e] * Cout + oc) * Cin + ic];
    __nv_bfloat16 h = __float2bfloat16(v);
    wh[idx] = h;
    wl[idx] = __float2bfloat16(v - __bfloat162float(h));
}

// transpose + split: X[b][K][1024] fp32 -> Xt hi/lo [b][1024][K] bf16
__global__ __launch_bounds__(256) void prep_x(const float* __restrict__ X,
    __nv_bfloat16* __restrict__ xh, __nv_bfloat16* __restrict__ xl,
    int K, int in_bs)
{
    __shared__ float t[32][33];
    int k0 = blockIdx.x * 32, n0 = blockIdx.y * 32, b = blockIdx.z;
    const float* Xb = X + (size_t)b * in_bs;
    int tid = threadIdx.x;
    int c = tid & 31, rbase = tid >> 5;
#pragma unroll
    for (int r = 0; r < 4; r++) {
        int row = rbase + r * 8;
        t[row][c] = Xb[(size_t)(k0 + row) * 1024 + n0 + c];
    }
    __syncthreads();
    size_t ob = (size_t)b * 1024 * K;
#pragma unroll
    for (int r = 0; r < 4; r++) {
        int nl = rbase + r * 8;
        float v = t[c][nl];
        __nv_bfloat16 h = __float2bfloat16(v);
        size_t oi = ob + (size_t)(n0 + nl) * K + k0 + c;
        xh[oi] = h;
        xl[oi] = __float2bfloat16(v - __bfloat162float(h));
    }
}

// ------------------------- mma.sync bf16 GEMM ------------------------------
// Y_b[M x 1024] = Weff * X_b (+bias). CTA 128x128, 8 warps (4m x 2n),
// warp 32x64, BK=32, 3-term split (AhBh + AhBl + AlBh).
// smem buffer 40960B: Ah(10240) Al(10240) Bh(10240) Bl(10240); rows 80B.
#define ROWB   80u
#define BUF_SZ 40960u
#define GEMM_SMEM (2 * 40960)

__device__ __forceinline__ void stage_issue(uint32_t smb, uint32_t boff,
    const __nv_bfloat16* __restrict__ wh, const __nv_bfloat16* __restrict__ wl,
    const __nv_bfloat16* __restrict__ xh, const __nv_bfloat16* __restrict__ xl,
    int K, int m0, int n0, int k0, int tid)
{
#pragma unroll
    for (int i = 0; i < 2; i++) {
        int cch = tid + 256 * i;
        int row = cch >> 2, j = cch & 3;
        uint32_t off = (uint32_t)row * ROWB + (uint32_t)(j << 4);
        size_t ga = (size_t)(m0 + row) * K + k0 + j * 8;
        size_t gb = (size_t)(n0 + row) * K + k0 + j * 8;
        cpa16(smb + boff + off,          wh + ga);
        cpa16(smb + boff + 10240 + off,  wl + ga);
        cpa16(smb + boff + 20480 + off,  xh + gb);
        cpa16(smb + boff + 30720 + off,  xl + gb);
    }
}

__global__ __launch_bounds__(256) void hgemm(
    const __nv_bfloat16* __restrict__ wh, const __nv_bfloat16* __restrict__ wl,
    const __nv_bfloat16* __restrict__ xh_, const __nv_bfloat16* __restrict__ xl_,
    float* __restrict__ Y, const float* __restrict__ bias,
    int K, int NS, int out_bs)
{
    extern __shared__ char sm[];
    const int tid  = threadIdx.x;
    const int b    = blockIdx.z;
    const int m0   = blockIdx.y * 128;
    const int n0   = blockIdx.x * 128;
    const __nv_bfloat16* xh = xh_ + (size_t)b * 1024 * K;
    const __nv_bfloat16* xl = xl_ + (size_t)b * 1024 * K;
    float* Yb = Y + (size_t)b * out_bs;
    const uint32_t smb = smem_u32(sm);

    const int lane = tid & 31;
    const int wrp  = tid >> 5;
    const int wm   = (wrp & 3) << 5;
    const int wn   = (wrp >> 2) << 6;

    float acc[2][8][4];
#pragma unroll
    for (int i = 0; i < 2; i++)
#pragma unroll
        for (int j = 0; j < 8; j++)
#pragma unroll
            for (int q = 0; q < 4; q++) acc[i][j][q] = 0.f;

    const int a_row = (lane & 15);
    const int a_kc  = (lane >> 4) << 3;
    const int b_row = (lane & 7) + ((lane >> 4) << 3);
    const int b_kc  = ((lane >> 3) & 1) << 3;

    stage_issue(smb, 0, wh, wl, xh, xl, K, m0, n0, 0, tid);
    CPA_COMMIT();

    for (int s = 0; s < NS; s++) {
        if (s + 1 < NS) {
            stage_issue(smb, (uint32_t)((s + 1) & 1) * BUF_SZ,
                        wh, wl, xh, xl, K, m0, n0, (s + 1) * 32, tid);
            CPA_COMMIT();
            CPA_WAIT(1);
        } else {
            CPA_WAIT(0);
        }
        __syncthreads();

        uint32_t base = smb + (uint32_t)(s & 1) * BUF_SZ;
        uint32_t Ah = base, Al = base + 10240;
        uint32_t Bh = base + 20480, Bl = base + 30720;

#pragma unroll
        for (int kk = 0; kk < 32; kk += 16) {
            uint32_t ah[2][4], al[2][4];
#pragma unroll
            for (int mt = 0; mt < 2; mt++) {
                uint32_t off = (uint32_t)(wm + mt * 16 + a_row) * ROWB +
                               (uint32_t)((kk + a_kc) << 1);
                ldm_x4(ah[mt], Ah + off);
                ldm_x4(al[mt], Al + off);
            }
#pragma unroll
            for (int gt = 0; gt < 4; gt++) {
                uint32_t off = (uint32_t)(wn + gt * 16 + b_row) * ROWB +
                               (uint32_t)((kk + b_kc) << 1);
                uint32_t bh[4], bl[4];
                ldm_x4(bh, Bh + off);
                ldm_x4(bl, Bl + off);
#pragma unroll
                for (int mt = 0; mt < 2; mt++) {
#pragma unroll
                    for (int h = 0; h < 2; h++) {
                        float* c = acc[mt][gt * 2 + h];
                        mma_bf16(c, ah[mt], bh[2 * h], bh[2 * h + 1]);
                        mma_bf16(c, ah[mt], bl[2 * h], bl[2 * h + 1]);
                        mma_bf16(c, al[mt], bh[2 * h], bh[2 * h + 1]);
                    }
                }
            }
        }
        __syncthreads();
    }

#pragma unroll
    for (int mt = 0; mt < 2; mt++) {
        int r0 = m0 + wm + mt * 16 + (lane >> 2);
        int r1 = r0 + 8;
        float bv0 = bias ? bias[r0] : 0.f;
        float bv1 = bias ? bias[r1] : 0.f;
        float* y0 = Yb + (size_t)r0 * 1024;
        float* y1 = Yb + (size_t)r1 * 1024;
#pragma unroll
        for (int nt = 0; nt < 8; nt++) {
            int col = n0 + wn + nt * 8 + ((lane & 3) << 1);
            float* c = acc[mt][nt];
            *(float2*)(y0 + col) = make_float2(c[0] + bv0, c[1] + bv0);
            *(float2*)(y1 + col) = make_float2(c[2] + bv1, c[3] + bv1);
        }
    }
}

// ------------------------------- IQBN --------------------------------------
__global__ __launch_bounds__(256) void iqbn_kernel(
    const float* __restrict__ x, float* __restrict__ y,
    const float* __restrict__ gam, const float* __restrict__ bet,
    int in_bs, int out_bs, int do_relu)
{
    int c4 = blockIdx.x;
    int tid = threadIdx.x;
    float v[16];
    float s = 0.f, ss = 0.f;
#pragma unroll
    for (int i = 0; i < 16; i++) {
        int e = tid + (i << 8);
        int bb = e >> 10, hw = e & 1023;
        float t = x[(size_t)bb * in_bs + (size_t)c4 * 1024 + hw];
        v[i] = t; s += t; ss += t * t;
    }
    __shared__ float rs[256], rq[256];
    rs[tid] = s; rq[tid] = ss;
    __syncthreads();
    for (int o = 128; o > 0; o >>= 1) {
        if (tid < o) { rs[tid] += rs[tid + o]; rq[tid] += rq[tid + o]; }
        __syncthreads();
    }
    float mean = rs[0] * (1.0f / 4096.0f);
    float var  = rq[0] * (1.0f / 4096.0f) - mean * mean;
    float rstd = rsqrtf(var + 1e-5f);
    float gg = gam[c4] * rstd;
    float bb2 = bet[c4] - mean * gg;
#pragma unroll
    for (int i = 0; i < 16; i++) {
        int e = tid + (i << 8);
        int bb = e >> 10, hw = e & 1023;
        float t = v[i] * gg + bb2;
        if (do_relu) t = fmaxf(t, 0.f);
        y[(size_t)bb * out_bs + (size_t)c4 * 1024 + hw] = t;
    }
}

// ----------------------------- attention -----------------------------------
// No online max (scores O(1), clamped exp); exp on FMA pipe.
__global__ __launch_bounds__(512) void attn_kernel(const float* __restrict__ qkv,
                                                   float* __restrict__ o)
{
    extern __shared__ float smf[];
    float* Ks = smf;
    float* Vs = smf + 16 * 1024;
    int combo = blockIdx.x;
    int qc = combo & 3;
    int hh = (combo >> 2) & 3;
    int bb = combo >> 4;
    int tid = threadIdx.x;
    const size_t cs = 4 * 1024;
    const float* qb = qkv + (((size_t)bb * 192 + hh * 48 +  0) * 4 + qc) * 1024;
    const float* kb = qkv + (((size_t)bb * 192 + hh * 48 + 16) * 4 + qc) * 1024;
    const float* vb = qkv + (((size_t)bb * 192 + hh * 48 + 32) * 4 + qc) * 1024;

    for (int i = tid; i < 16 * 1024; i += 512) {
        int d = i >> 10, m = i & 1023;
        Ks[i] = kb[d * cs + m];
        Vs[i] = vb[d * cs + m];
    }
    __syncthreads();

    int n = blockIdx.y * 512 + tid;
    ull qp[16];
#pragma unroll
    for (int d = 0; d < 16; d++) {
        float qd = qb[d * cs + n] * 0.25f;
        qp[d] = pk2(qd, qd);
    }

    float l = 0.f;
    ull acc2[16];
#pragma unroll
    for (int d = 0; d < 16; d++) acc2[d] = 0ull;

    for (int mv = 0; mv < 256; mv++) {
        ull s01 = 0ull, s23 = 0ull;
#pragma unroll
        for (int d = 0; d < 16; d++) {
            ulonglong2 kv = *(const ulonglong2*)&Ks[d * 1024 + mv * 4];
            s01 = fma2(qp[d], kv.x, s01);
            s23 = fma2(qp[d], kv.y, s23);
        }
        float2 sA = upk2(s01), sB = upk2(s23);
        float p0 = fexp(sA.x);
        float p1 = fexp(sA.y);
        float p2 = fexp(sB.x);
        float p3 = fexp(sB.y);
        l += (p0 + p1) + (p2 + p3);
        ull p01 = pk2(p0, p1), p23 = pk2(p2, p3);
#pragma unroll
        for (int d = 0; d < 16; d++) {
            ulonglong2 vv = *(const ulonglong2*)&Vs[d * 1024 + mv * 4];
            acc2[d] = fma2(p01, vv.x, acc2[d]);
            acc2[d] = fma2(p23, vv.y, acc2[d]);
        }
    }
    float inv = 1.f / l;
#pragma unroll
    for (int d = 0; d < 16; d++) {
        float2 a = upk2(acc2[d]);
        o[(((size_t)bb * 64 + hh * 16 + d) * 4 + qc) * 1024 + n] = (a.x + a.y) * inv;
    }
}

// --------------------- 3x3 grouped quaternion PE conv ----------------------
__global__ __launch_bounds__(1024) void pe_kernel(
    const float* __restrict__ o, const float* __restrict__ pw,
    const float* __restrict__ pb, float* __restrict__ o2)
{
    int blk = blockIdx.x;
    int co = blk & 3;
    int oc = (blk >> 2) & 63;
    int bb = blk >> 8;
    int t = threadIdx.x;
    int y = t >> 5, xq = t & 31;
    int g = oc >> 2;

    float acc = pb[oc * 4 + co];
#pragma unroll
    for (int ci = 0; ci < 4; ci++) {
        int wc  = c_WIDX[co * 4 + ci];
        float s = c_SGN [co * 4 + ci];
#pragma unroll
        for (int ic = 0; ic < 4; ic++) {
            const float* xp = o  + (((size_t)bb * 64 + g * 4 + ic) * 4 + ci) * 1024;
            const float* wp = pw + (((size_t)wc * 64 + oc) * 4 + ic) * 9;
            float sum = 0.f;
#pragma unroll
            for (int ky = 0; ky < 3; ky++) {
                int yy = y + ky - 1;
                if (yy < 0 || yy > 31) continue;
#pragma unroll
                for (int kx = 0; kx < 3; kx++) {
                    int xx = xq + kx - 1;
                    if (xx < 0 || xx > 31) continue;
                    sum += xp[yy * 32 + xx] * wp[ky * 3 + kx];
                }
            }
            acc += s * sum;
        }
    }
    size_t oi = (((size_t)bb * 64 + oc) * 4 + co) * 1024 + t;
    o2[oi] = o[oi] + acc;
}

// ---------------------- copy b-branch into concat --------------------------
__global__ void copy_b_kernel(const float* __restrict__ h1, float* __restrict__ cat)
{
    int i = blockIdx.x * blockDim.x + threadIdx.x;
    int hw = i & 1023;
    int c4 = (i >> 10) & 255;
    int bb = i >> 18;
    size_t off = ((size_t)bb * 512 + 256 + c4) * 1024 + hw;
    cat[off] = h1[off];
}

// ---------------------------------------------------------------------------
static void run_gemm(const float* w, const float* X, float* Y, const float* bias,
                     int Cout, int Cin, int in_bs, int out_bs,
                     __nv_bfloat16* wh, __nv_bfloat16* wl,
                     __nv_bfloat16* xh, __nv_bfloat16* xl)
{
    int K = Cin * 4, M = Cout * 4;
    prep_w<<<(M * K + 255) / 256, 256>>>(w, wh, wl, Cout, Cin);
    prep_x<<<dim3(K / 32, 32, 4), 256>>>(X, xh, xl, K, in_bs);
    hgemm<<<dim3(8, M / 128, 4), 256, GEMM_SMEM>>>(wh, wl, xh, xl, Y, bias,
                                                   K, K / 32, out_bs);
}

extern "C" void kernel_launch(void* const* d_in, const int* in_sizes, int n_in,
                              void* d_out, int out_size)
{
    const float* x      = (const float*)d_in[0];
    const float* cv1_w  = (const float*)d_in[1];
    const float* bn1_g  = (const float*)d_in[2];
    const float* bn1_b  = (const float*)d_in[3];
    const float* qkv_w  = (const float*)d_in[4];
    const float* qkv_b  = (const float*)d_in[5];
    const float* proj_w = (const float*)d_in[6];
    const float* proj_b = (const float*)d_in[7];
    const float* pe_w   = (const float*)d_in[8];
    const float* pe_b   = (const float*)d_in[9];
    const float* an_g   = (const float*)d_in[10];
    const float* an_b   = (const float*)d_in[11];
    const float* ffn1_w = (const float*)d_in[12];
    const float* fbn1_g = (const float*)d_in[13];
    const float* fbn1_b = (const float*)d_in[14];
    const float* ffn2_w = (const float*)d_in[15];
    const float* fbn2_g = (const float*)d_in[16];
    const float* fbn2_b = (const float*)d_in[17];
    const float* cv2_w  = (const float*)d_in[18];
    const float* bn2_g  = (const float*)d_in[19];
    const float* bn2_b  = (const float*)d_in[20];
    float* out = (float*)d_out;

    float *h1, *qkv, *o, *o2, *p, *f1, *cat;
    __nv_bfloat16 *wh, *wl, *xh, *xl;
    cudaGetSymbolAddress((void**)&h1,  g_h1);
    cudaGetSymbolAddress((void**)&qkv, g_qkv);
    cudaGetSymbolAddress((void**)&o,   g_o);
    cudaGetSymbolAddress((void**)&o2,  g_o2);
    cudaGetSymbolAddress((void**)&p,   g_p);
    cudaGetSymbolAddress((void**)&f1,  g_f1);
    cudaGetSymbolAddress((void**)&cat, g_cat);
    cudaGetSymbolAddress((void**)&wh,  g_wh);
    cudaGetSymbolAddress((void**)&wl,  g_wl);
    cudaGetSymbolAddress((void**)&xh,  g_xh);
    cudaGetSymbolAddress((void**)&xl,  g_xl);

    cudaFuncSetAttribute(hgemm, cudaFuncAttributeMaxDynamicSharedMemorySize,
                         GEMM_SMEM);
    cudaFuncSetAttribute(attn_kernel, cudaFuncAttributeMaxDynamicSharedMemorySize,
                         131072);

    const int BS512 = 512 * 1024;
    const int BS768 = 768 * 1024;
    const int BS256 = 256 * 1024;

    // 1) cv1 + bn1 + relu -> h1
    run_gemm(cv1_w, x, h1, nullptr, 128, 128, BS512, BS512, wh, wl, xh, xl);
    iqbn_kernel<<<512, 256>>>(h1, h1, bn1_g, bn1_b, BS512, BS512, 1);

    // 2) qkv (a-branch = h1 rows 0..255)
    run_gemm(qkv_w, h1, qkv, qkv_b, 192, 64, BS512, BS768, wh, wl, xh, xl);

    // 3) attention -> o
    attn_kernel<<<dim3(64, 2), 512, 131072>>>(qkv, o);

    // 4) o2 = o + pe(o) + pe_b
    pe_kernel<<<1024, 1024>>>(o, pe_w, pe_b, o2);

    // 5) proj + attn_norm
    run_gemm(proj_w, o2, p, proj_b, 64, 64, BS256, BS256, wh, wl, xh, xl);
    iqbn_kernel<<<256, 256>>>(p, p, an_g, an_b, BS256, BS256, 0);

    // 6) ffn1 + bn + relu
    run_gemm(ffn1_w, p, f1, nullptr, 128, 64, BS256, BS512, wh, wl, xh, xl);
    iqbn_kernel<<<512, 256>>>(f1, f1, fbn1_g, fbn1_b, BS512, BS512, 1);

    // 7) ffn2 -> o, bn -> cat rows 0..255
    run_gemm(ffn2_w, f1, o, nullptr, 64, 128, BS512, BS256, wh, wl, xh, xl);
    iqbn_kernel<<<256, 256>>>(o, cat, fbn2_g, fbn2_b, BS256, BS512, 0);

    // 8) concat b-branch
    copy_b_kernel<<<4096, 256>>>(h1, cat);

    // 9) cv2 + bn2 + relu -> out
    run_gemm(cv2_w, cat, f1, nullptr, 128, 128, BS512, BS512, wh, wl, xh, xl);
    iqbn_kernel<<<512, 256>>>(f1, out, bn2_g, bn2_b, BS512, BS512, 1);
}

// round 13
// speedup vs baseline: 1.5928x; 1.0617x over previous
#include <cuda_runtime.h>
#include <cuda_bf16.h>
#include <math.h>
#include <stdint.h>

typedef unsigned long long ull;

// ---------------------------------------------------------------------------
// PSA quaternion block. activations [B=4, C, 4, 1024] fp32 = per-batch
// row-major (C*4) x 1024. 1x1 qconvs -> bf16 split HMMA GEMMs (3-term).
// IQBN stats fused into GEMM epilogue (atomics); BN apply fused into the
// consumer GEMM's prep_x. 4-deep cp.async pipeline.
// ---------------------------------------------------------------------------

__constant__ int   c_WIDX[16] = {0,1,2,3,  1,0,3,2,  2,3,0,1,  3,2,1,0};
__constant__ float c_SGN [16] = {1,-1,-1,-1,  1,1,1,-1,  1,-1,1,1,  1,1,-1,1};

// ------------------------------ scratch ------------------------------------
__device__ float g_h1 [4*512*1024];   // cv1 raw out
__device__ float g_qkv[4*768*1024];
__device__ float g_o  [4*256*1024];   // attn out; reused for ffn2 raw out
__device__ float g_o2 [4*256*1024];   // o + pe
__device__ float g_p  [4*256*1024];   // proj raw out
__device__ float g_f1 [4*512*1024];   // ffn1 raw out; reused cv2 raw out
__device__ __nv_bfloat16 g_whp[1048576];
__device__ __nv_bfloat16 g_wlp[1048576];
__device__ __nv_bfloat16 g_xh[4*1024*512];
__device__ __nv_bfloat16 g_xl[4*1024*512];
__device__ float  g_stats[5*1024];    // per-bn: 1024 floats (row sum,sumsq)
__device__ float4 g_prm [2560];       // per-bn params (gg,bb,rlim,_)

// weight pool offsets (elements)
#define WO_CV1  0
#define WO_QKV  262144
#define WO_PROJ 458752
#define WO_FFN1 524288
#define WO_FFN2 655360
#define WO_CV2  786432
// stats offsets (floats)
#define SO_BN1  0
#define SO_AN   1024
#define SO_FBN1 2048
#define SO_FBN2 3072
#define SO_BN2  4096
// param offsets (float4)
#define PO_BN1  0
#define PO_AN   512
#define PO_FBN1 768
#define PO_FBN2 1280
#define PO_BN2  1536

// --------------------------- helpers ---------------------------------------
__device__ __forceinline__ uint32_t smem_u32(const void* p) {
    uint32_t a;
    asm("{ .reg .u64 t; cvta.to.shared.u64 t, %1; cvt.u32.u64 %0, t; }"
        : "=r"(a) : "l"(p));
    return a;
}
__device__ __forceinline__ void ldm_x4(uint32_t* r, uint32_t addr) {
    asm volatile("ldmatrix.sync.aligned.m8n8.x4.shared.b16 {%0,%1,%2,%3}, [%4];"
                 : "=r"(r[0]), "=r"(r[1]), "=r"(r[2]), "=r"(r[3]) : "r"(addr));
}
__device__ __forceinline__ void mma_bf16(float* c, const uint32_t* a,
                                         uint32_t b0, uint32_t b1) {
    asm volatile(
        "mma.sync.aligned.m16n8k16.row.col.f32.bf16.bf16.f32 "
        "{%0,%1,%2,%3}, {%4,%5,%6,%7}, {%8,%9}, {%0,%1,%2,%3};"
        : "+f"(c[0]), "+f"(c[1]), "+f"(c[2]), "+f"(c[3])
        : "r"(a[0]), "r"(a[1]), "r"(a[2]), "r"(a[3]), "r"(b0), "r"(b1));
}
__device__ __forceinline__ void cpa16(uint32_t sa, const void* g) {
    asm volatile("cp.async.ca.shared.global [%0], [%1], 16;"
                 :: "r"(sa), "l"(g) : "memory");
}
#define CPA_COMMIT() asm volatile("cp.async.commit_group;" ::: "memory")
#define CPA_WAIT(n)  asm volatile("cp.async.wait_group %0;" :: "n"(n) : "memory")

// f32x2 packed math (attention)
__device__ __forceinline__ ull fma2(ull a, ull b, ull c) {
    ull d; asm("fma.rn.f32x2 %0, %1, %2, %3;" : "=l"(d) : "l"(a), "l"(b), "l"(c));
    return d;
}
__device__ __forceinline__ ull pk2(float lo, float hi) {
    ull r; asm("mov.b64 %0, {%1, %2};" : "=l"(r) : "f"(lo), "f"(hi));
    return r;
}
__device__ __forceinline__ float2 upk2(ull a) {
    float lo, hi; asm("mov.b64 {%0, %1}, %2;" : "=f"(lo), "=f"(hi) : "l"(a));
    return make_float2(lo, hi);
}

// ------------------------- prep kernels ------------------------------------
__global__ void zero_stats() {
    int i = blockIdx.x * blockDim.x + threadIdx.x;
    if (i < 5 * 1024) g_stats[i] = 0.f;
}

__device__ __forceinline__ void expand_one(const float* w, int Cout, int Cin,
                                           int lidx, __nv_bfloat16* wh,
                                           __nv_bfloat16* wl)
{
    int K = Cin * 4;
    int k = lidx % K, m = lidx / K;
    int oc = m >> 2, co = m & 3;
    int ic = k >> 2, ci = k & 3;
    int e = co * 4 + ci;
    float v = c_SGN[e] * w[((size_t)c_WIDX[e] * Cout + oc) * Cin + ic];
    __nv_bfloat16 h = __float2bfloat16(v);
    wh[lidx] = h;
    wl[lidx] = __float2bfloat16(v - __bfloat162float(h));
}

__global__ void prep_w_all(const float* w1, const float* w2, const float* w3,
                           const float* w4, const float* w5, const float* w6)
{
    int i = blockIdx.x * blockDim.x + threadIdx.x;
    if (i >= 1048576) return;
    __nv_bfloat16* wh = g_whp;
    __nv_bfloat16* wl = g_wlp;
    if      (i < WO_QKV)  expand_one(w1, 128, 128, i - WO_CV1,  wh + WO_CV1,  wl + WO_CV1);
    else if (i < WO_PROJ) expand_one(w2, 192,  64, i - WO_QKV,  wh + WO_QKV,  wl + WO_QKV);
    else if (i < WO_FFN1) expand_one(w3,  64,  64, i - WO_PROJ, wh + WO_PROJ, wl + WO_PROJ);
    else if (i < WO_FFN2) expand_one(w4, 128,  64, i - WO_FFN1, wh + WO_FFN1, wl + WO_FFN1);
    else if (i < WO_CV2)  expand_one(w5,  64, 128, i - WO_FFN2, wh + WO_FFN2, wl + WO_FFN2);
    else                  expand_one(w6, 128, 128, i - WO_CV2,  wh + WO_CV2,  wl + WO_CV2);
}

// finalize bn params from stats
__global__ void fin_bn(const float* __restrict__ stats,
                       const float* __restrict__ g, const float* __restrict__ b,
                       float4* __restrict__ prm, int rows, float rlim)
{
    int r = blockIdx.x * blockDim.x + threadIdx.x;
    if (r >= rows) return;
    float s = stats[2 * r], ss = stats[2 * r + 1];
    float mean = s * (1.f / 4096.f);
    float var  = ss * (1.f / 4096.f) - mean * mean;
    float gg = g[r] * rsqrtf(var + 1e-5f);
    float bb = b[r] - mean * gg;
    prm[r] = make_float4(gg, bb, rlim, 0.f);
}

// transpose + optional bn-apply + bf16 split:
// src X[b][Ksrc rows][1024] (batch stride sbs) -> dst [b][1024][Ktot] at kdst.
__global__ __launch_bounds__(256) void prep_x(const float* __restrict__ X,
    const float4* __restrict__ prm,
    __nv_bfloat16* __restrict__ xh, __nv_bfloat16* __restrict__ xl,
    int sbs, int Ktot, int kdst)
{
    __shared__ float t[32][33];
    int k0 = blockIdx.x * 32, n0 = blockIdx.y * 32, b = blockIdx.z;
    const float* Xb = X + (size_t)b * sbs;
    int tid = threadIdx.x;
    int c = tid & 31, rbase = tid >> 5;
#pragma unroll
    for (int r = 0; r < 4; r++) {
        int row = rbase + r * 8;
        t[row][c] = Xb[(size_t)(k0 + row) * 1024 + n0 + c];
    }
    __syncthreads();
    float gg = 1.f, bb = 0.f, rl = -1e30f;
    if (prm) { float4 pr = prm[k0 + c]; gg = pr.x; bb = pr.y; rl = pr.z; }
    size_t ob = (size_t)b * 1024 * Ktot;
#pragma unroll
    for (int r = 0; r < 4; r++) {
        int nl = rbase + r * 8;
        float v = fmaxf(fmaf(gg, t[c][nl], bb), rl);
        __nv_bfloat16 h = __float2bfloat16(v);
        size_t oi = ob + (size_t)(n0 + nl) * Ktot + kdst + k0 + c;
        xh[oi] = h;
        xl[oi] = __float2bfloat16(v - __bfloat162float(h));
    }
}

// ------------------------- mma.sync bf16 GEMM ------------------------------
// CTA 128x128, 8 warps (4m x 2n), warp 32x64, BK=32, 4-stage cp.async.
#define ROWB   80u
#define BUF_SZ 40960u
#define GEMM_SMEM (4 * 40960)

__device__ __forceinline__ void stage_issue(uint32_t smb, uint32_t boff,
    const __nv_bfloat16* __restrict__ wh, const __nv_bfloat16* __restrict__ wl,
    const __nv_bfloat16* __restrict__ xh, const __nv_bfloat16* __restrict__ xl,
    int K, int m0, int n0, int k0, int tid)
{
#pragma unroll
    for (int i = 0; i < 2; i++) {
        int cch = tid + 256 * i;
        int row = cch >> 2, j = cch & 3;
        uint32_t off = (uint32_t)row * ROWB + (uint32_t)(j << 4);
        size_t ga = (size_t)(m0 + row) * K + k0 + j * 8;
        size_t gb = (size_t)(n0 + row) * K + k0 + j * 8;
        cpa16(smb + boff + off,          wh + ga);
        cpa16(smb + boff + 10240 + off,  wl + ga);
        cpa16(smb + boff + 20480 + off,  xh + gb);
        cpa16(smb + boff + 30720 + off,  xl + gb);
    }
}

__global__ __launch_bounds__(256) void hgemm(
    const __nv_bfloat16* __restrict__ wh, const __nv_bfloat16* __restrict__ wl,
    const __nv_bfloat16* __restrict__ xh_, const __nv_bfloat16* __restrict__ xl_,
    float* __restrict__ Y, const float* __restrict__ bias,
    float* __restrict__ stats, int K, int NS, int out_bs)
{
    extern __shared__ char sm[];
    const int tid  = threadIdx.x;
    const int b    = blockIdx.z;
    const int m0   = blockIdx.y * 128;
    const int n0   = blockIdx.x * 128;
    const __nv_bfloat16* xh = xh_ + (size_t)b * 1024 * K;
    const __nv_bfloat16* xl = xl_ + (size_t)b * 1024 * K;
    float* Yb = Y + (size_t)b * out_bs;
    const uint32_t smb = smem_u32(sm);

    const int lane = tid & 31;
    const int wrp  = tid >> 5;
    const int wm   = (wrp & 3) << 5;
    const int wn   = (wrp >> 2) << 6;

    float acc[2][8][4];
#pragma unroll
    for (int i = 0; i < 2; i++)
#pragma unroll
        for (int j = 0; j < 8; j++)
#pragma unroll
            for (int q = 0; q < 4; q++) acc[i][j][q] = 0.f;

    const int a_row = (lane & 15);
    const int a_kc  = (lane >> 4) << 3;
    const int b_row = (lane & 7) + ((lane >> 4) << 3);
    const int b_kc  = ((lane >> 3) & 1) << 3;

#pragma unroll
    for (int i = 0; i < 3; i++) {
        if (i < NS)
            stage_issue(smb, (uint32_t)i * BUF_SZ, wh, wl, xh, xl,
                        K, m0, n0, i * 32, tid);
        CPA_COMMIT();
    }

    for (int s = 0; s < NS; s++) {
        CPA_WAIT(2);
        __syncthreads();
        if (s + 3 < NS)
            stage_issue(smb, (uint32_t)((s + 3) & 3) * BUF_SZ,
                        wh, wl, xh, xl, K, m0, n0, (s + 3) * 32, tid);
        CPA_COMMIT();

        uint32_t base = smb + (uint32_t)(s & 3) * BUF_SZ;
        uint32_t Ah = base, Al = base + 10240;
        uint32_t Bh = base + 20480, Bl = base + 30720;

#pragma unroll
        for (int kk = 0; kk < 32; kk += 16) {
            uint32_t ah[2][4], al[2][4];
#pragma unroll
            for (int mt = 0; mt < 2; mt++) {
                uint32_t off = (uint32_t)(wm + mt * 16 + a_row) * ROWB +
                               (uint32_t)((kk + a_kc) << 1);
                ldm_x4(ah[mt], Ah + off);
                ldm_x4(al[mt], Al + off);
            }
#pragma unroll
            for (int gt = 0; gt < 4; gt++) {
                uint32_t off = (uint32_t)(wn + gt * 16 + b_row) * ROWB +
                               (uint32_t)((kk + b_kc) << 1);
                uint32_t bh[4], bl[4];
                ldm_x4(bh, Bh + off);
                ldm_x4(bl, Bl + off);
#pragma unroll
                for (int mt = 0; mt < 2; mt++) {
#pragma unroll
                    for (int h = 0; h < 2; h++) {
                        float* c = acc[mt][gt * 2 + h];
                        mma_bf16(c, ah[mt], bh[2 * h], bh[2 * h + 1]);
                        mma_bf16(c, ah[mt], bl[2 * h], bl[2 * h + 1]);
                        mma_bf16(c, al[mt], bh[2 * h], bh[2 * h + 1]);
                    }
                }
            }
        }
        __syncthreads();
    }

#pragma unroll
    for (int mt = 0; mt < 2; mt++) {
        int r0 = m0 + wm + mt * 16 + (lane >> 2);
        int r1 = r0 + 8;
        float bv0 = bias ? bias[r0] : 0.f;
        float bv1 = bias ? bias[r1] : 0.f;
        float* y0 = Yb + (size_t)r0 * 1024;
        float* y1 = Yb + (size_t)r1 * 1024;
        float s0 = 0.f, q0 = 0.f, s1 = 0.f, q1 = 0.f;
#pragma unroll
        for (int nt = 0; nt < 8; nt++) {
            int col = n0 + wn + nt * 8 + ((lane & 3) << 1);
            float* c = acc[mt][nt];
            float v0 = c[0] + bv0, v1 = c[1] + bv0;
            float v2 = c[2] + bv1, v3 = c[3] + bv1;
            *(float2*)(y0 + col) = make_float2(v0, v1);
            *(float2*)(y1 + col) = make_float2(v2, v3);
            s0 += v0 + v1; q0 += v0 * v0 + v1 * v1;
            s1 += v2 + v3; q1 += v2 * v2 + v3 * v3;
        }
        if (stats) {
            s0 += __shfl_xor_sync(0xFFFFFFFF, s0, 1);
            s0 += __shfl_xor_sync(0xFFFFFFFF, s0, 2);
            q0 += __shfl_xor_sync(0xFFFFFFFF, q0, 1);
            q0 += __shfl_xor_sync(0xFFFFFFFF, q0, 2);
            s1 += __shfl_xor_sync(0xFFFFFFFF, s1, 1);
            s1 += __shfl_xor_sync(0xFFFFFFFF, s1, 2);
            q1 += __shfl_xor_sync(0xFFFFFFFF, q1, 1);
            q1 += __shfl_xor_sync(0xFFFFFFFF, q1, 2);
            if ((lane & 3) == 0) {
                atomicAdd(&stats[2 * r0],     s0);
                atomicAdd(&stats[2 * r0 + 1], q0);
                atomicAdd(&stats[2 * r1],     s1);
                atomicAdd(&stats[2 * r1 + 1], q1);
            }
        }
    }
}

// ----------------------------- attention -----------------------------------
// No online max (scores O(1)); MUFU exp; f32x2 packed QK/PV.
__global__ __launch_bounds__(512) void attn_kernel(const float* __restrict__ qkv,
                                                   float* __restrict__ o)
{
    extern __shared__ float smf[];
    float* Ks = smf;
    float* Vs = smf + 16 * 1024;
    int combo = blockIdx.x;
    int qc = combo & 3;
    int hh = (combo >> 2) & 3;
    int bb = combo >> 4;
    int tid = threadIdx.x;
    const size_t cs = 4 * 1024;
    const float* qb = qkv + (((size_t)bb * 192 + hh * 48 +  0) * 4 + qc) * 1024;
    const float* kb = qkv + (((size_t)bb * 192 + hh * 48 + 16) * 4 + qc) * 1024;
    const float* vb = qkv + (((size_t)bb * 192 + hh * 48 + 32) * 4 + qc) * 1024;

    for (int i = tid; i < 16 * 1024; i += 512) {
        int d = i >> 10, m = i & 1023;
        Ks[i] = kb[d * cs + m];
        Vs[i] = vb[d * cs + m];
    }
    __syncthreads();

    int n = blockIdx.y * 512 + tid;
    ull qp[16];
#pragma unroll
    for (int d = 0; d < 16; d++) {
        float qd = qb[d * cs + n] * 0.25f;
        qp[d] = pk2(qd, qd);
    }

    float l = 0.f;
    ull acc2[16];
#pragma unroll
    for (int d = 0; d < 16; d++) acc2[d] = 0ull;

    for (int mv = 0; mv < 256; mv++) {
        ull s01 = 0ull, s23 = 0ull;
#pragma unroll
        for (int d = 0; d < 16; d++) {
            ulonglong2 kv = *(const ulonglong2*)&Ks[d * 1024 + mv * 4];
            s01 = fma2(qp[d], kv.x, s01);
            s23 = fma2(qp[d], kv.y, s23);
        }
        float2 sA = upk2(s01), sB = upk2(s23);
        float p0 = __expf(sA.x);
        float p1 = __expf(sA.y);
        float p2 = __expf(sB.x);
        float p3 = __expf(sB.y);
        l += (p0 + p1) + (p2 + p3);
        ull p01 = pk2(p0, p1), p23 = pk2(p2, p3);
#pragma unroll
        for (int d = 0; d < 16; d++) {
            ulonglong2 vv = *(const ulonglong2*)&Vs[d * 1024 + mv * 4];
            acc2[d] = fma2(p01, vv.x, acc2[d]);
            acc2[d] = fma2(p23, vv.y, acc2[d]);
        }
    }
    float inv = 1.f / l;
#pragma unroll
    for (int d = 0; d < 16; d++) {
        float2 a = upk2(acc2[d]);
        o[(((size_t)bb * 64 + hh * 16 + d) * 4 + qc) * 1024 + n] = (a.x + a.y) * inv;
    }
}

// --------------------- 3x3 grouped quaternion PE conv ----------------------
__global__ __launch_bounds__(1024) void pe_kernel(
    const float* __restrict__ o, const float* __restrict__ pw,
    const float* __restrict__ pb, float* __restrict__ o2)
{
    int blk = blockIdx.x;
    int co = blk & 3;
    int oc = (blk >> 2) & 63;
    int bb = blk >> 8;
    int t = threadIdx.x;
    int y = t >> 5, xq = t & 31;
    int g = oc >> 2;

    float acc = pb[oc * 4 + co];
#pragma unroll
    for (int ci = 0; ci < 4; ci++) {
        int wc  = c_WIDX[co * 4 + ci];
        float s = c_SGN [co * 4 + ci];
#pragma unroll
        for (int ic = 0; ic < 4; ic++) {
            const float* xp = o  + (((size_t)bb * 64 + g * 4 + ic) * 4 + ci) * 1024;
            const float* wp = pw + (((size_t)wc * 64 + oc) * 4 + ic) * 9;
            float sum = 0.f;
#pragma unroll
            for (int ky = 0; ky < 3; ky++) {
                int yy = y + ky - 1;
                if (yy < 0 || yy > 31) continue;
#pragma unroll
                for (int kx = 0; kx < 3; kx++) {
                    int xx = xq + kx - 1;
                    if (xx < 0 || xx > 31) continue;
                    sum += xp[yy * 32 + xx] * wp[ky * 3 + kx];
                }
            }
            acc += s * sum;
        }
    }
    size_t oi = (((size_t)bb * 64 + oc) * 4 + co) * 1024 + t;
    o2[oi] = o[oi] + acc;
}

// ---------------------- final bn apply (bn2) --------------------------------
__global__ void apply_bn(const float* __restrict__ x, float* __restrict__ y,
                         const float4* __restrict__ prm)
{
    int i = blockIdx.x * blockDim.x + threadIdx.x;  // < 2097152
    int c4 = (i >> 10) & 511;
    float4 pr = prm[c4];
    y[i] = fmaxf(fmaf(pr.x, x[i], pr.y), pr.z);
}

// ---------------------------------------------------------------------------
extern "C" void kernel_launch(void* const* d_in, const int* in_sizes, int n_in,
                              void* d_out, int out_size)
{
    const float* x      = (const float*)d_in[0];
    const float* cv1_w  = (const float*)d_in[1];
    const float* bn1_g  = (const float*)d_in[2];
    const float* bn1_b  = (const float*)d_in[3];
    const float* qkv_w  = (const float*)d_in[4];
    const float* qkv_b  = (const float*)d_in[5];
    const float* proj_w = (const float*)d_in[6];
    const float* proj_b = (const float*)d_in[7];
    const float* pe_w   = (const float*)d_in[8];
    const float* pe_b   = (const float*)d_in[9];
    const float* an_g   = (const float*)d_in[10];
    const float* an_b   = (const float*)d_in[11];
    const float* ffn1_w = (const float*)d_in[12];
    const float* fbn1_g = (const float*)d_in[13];
    const float* fbn1_b = (const float*)d_in[14];
    const float* ffn2_w = (const float*)d_in[15];
    const float* fbn2_g = (const float*)d_in[16];
    const float* fbn2_b = (const float*)d_in[17];
    const float* cv2_w  = (const float*)d_in[18];
    const float* bn2_g  = (const float*)d_in[19];
    const float* bn2_b  = (const float*)d_in[20];
    float* out = (float*)d_out;

    float *h1, *qkv, *o, *o2, *p, *f1, *stats;
    float4* prm;
    __nv_bfloat16 *wh, *wl, *xh, *xl;
    cudaGetSymbolAddress((void**)&h1,  g_h1);
    cudaGetSymbolAddress((void**)&qkv, g_qkv);
    cudaGetSymbolAddress((void**)&o,   g_o);
    cudaGetSymbolAddress((void**)&o2,  g_o2);
    cudaGetSymbolAddress((void**)&p,   g_p);
    cudaGetSymbolAddress((void**)&f1,  g_f1);
    cudaGetSymbolAddress((void**)&wh,  g_whp);
    cudaGetSymbolAddress((void**)&wl,  g_wlp);
    cudaGetSymbolAddress((void**)&xh,  g_xh);
    cudaGetSymbolAddress((void**)&xl,  g_xl);
    cudaGetSymbolAddress((void**)&stats, g_stats);
    cudaGetSymbolAddress((void**)&prm,   g_prm);

    cudaFuncSetAttribute(hgemm, cudaFuncAttributeMaxDynamicSharedMemorySize,
                         GEMM_SMEM);
    cudaFuncSetAttribute(attn_kernel, cudaFuncAttributeMaxDynamicSharedMemorySize,
                         131072);

    const int BS512 = 512 * 1024;
    const int BS768 = 768 * 1024;
    const int BS256 = 256 * 1024;
    const float NORELU = -1e30f;

    // 0) weight expansion (all 6) + stats zero
    prep_w_all<<<4096, 256>>>(cv1_w, qkv_w, proj_w, ffn1_w, ffn2_w, cv2_w);
    zero_stats<<<20, 256>>>();

    // 1) cv1 -> h1 raw (+bn1 stats)
    prep_x<<<dim3(16, 32, 4), 256>>>(x, nullptr, xh, xl, BS512, 512, 0);
    hgemm<<<dim3(8, 4, 4), 256, GEMM_SMEM>>>(wh + WO_CV1, wl + WO_CV1, xh, xl,
                                             h1, nullptr, stats + SO_BN1,
                                             512, 16, BS512);
    fin_bn<<<4, 128>>>(stats + SO_BN1, bn1_g, bn1_b, prm + PO_BN1, 512, 0.f);

    // 2) qkv = W * relu(bn1(h1[0:256]))  (apply fused in prep_x)
    prep_x<<<dim3(8, 32, 4), 256>>>(h1, prm + PO_BN1, xh, xl, BS512, 256, 0);
    hgemm<<<dim3(8, 6, 4), 256, GEMM_SMEM>>>(wh + WO_QKV, wl + WO_QKV, xh, xl,
                                             qkv, qkv_b, nullptr,
                                             256, 8, BS768);

    // 3) attention -> o
    attn_kernel<<<dim3(64, 2), 512, 131072>>>(qkv, o);

    // 4) o2 = o + pe(o) + pe_b
    pe_kernel<<<1024, 1024>>>(o, pe_w, pe_b, o2);

    // 5) proj(o2) -> p raw (+attn_norm stats)
    prep_x<<<dim3(8, 32, 4), 256>>>(o2, nullptr, xh, xl, BS256, 256, 0);
    hgemm<<<dim3(8, 2, 4), 256, GEMM_SMEM>>>(wh + WO_PROJ, wl + WO_PROJ, xh, xl,
                                             p, proj_b, stats + SO_AN,
                                             256, 8, BS256);
    fin_bn<<<2, 128>>>(stats + SO_AN, an_g, an_b, prm + PO_AN, 256, NORELU);

    // 6) ffn1(attn_norm(p)) -> f1 raw (+fbn1 stats)
    prep_x<<<dim3(8, 32, 4), 256>>>(p, prm + PO_AN, xh, xl, BS256, 256, 0);
    hgemm<<<dim3(8, 4, 4), 256, GEMM_SMEM>>>(wh + WO_FFN1, wl + WO_FFN1, xh, xl,
                                             f1, nullptr, stats + SO_FBN1,
                                             256, 8, BS512);
    fin_bn<<<4, 128>>>(stats + SO_FBN1, fbn1_g, fbn1_b, prm + PO_FBN1, 512, 0.f);

    // 7) ffn2(relu(fbn1(f1))) -> o raw (+fbn2 stats)
    prep_x<<<dim3(16, 32, 4), 256>>>(f1, prm + PO_FBN1, xh, xl, BS512, 512, 0);
    hgemm<<<dim3(8, 2, 4), 256, GEMM_SMEM>>>(wh + WO_FFN2, wl + WO_FFN2, xh, xl,
                                             o, nullptr, stats + SO_FBN2,
                                             512, 16, BS256);
    fin_bn<<<2, 128>>>(stats + SO_FBN2, fbn2_g, fbn2_b, prm + PO_FBN2, 256, NORELU);

    // 8) cv2(concat(fbn2(o), relu(bn1(h1[256:512])))) -> f1 raw (+bn2 stats)
    prep_x<<<dim3(8, 32, 4), 256>>>(o, prm + PO_FBN2, xh, xl, BS256, 512, 0);
    prep_x<<<dim3(8, 32, 4), 256>>>(h1 + 256 * 1024, prm + PO_BN1 + 256,
                                    xh, xl, BS512, 512, 256);
    hgemm<<<dim3(8, 4, 4), 256, GEMM_SMEM>>>(wh + WO_CV2, wl + WO_CV2, xh, xl,
                                             f1, nullptr, stats + SO_BN2,
                                             512, 16, BS512);
    fin_bn<<<4, 128>>>(stats + SO_BN2, bn2_g, bn2_b, prm + PO_BN2, 512, 0.f);

    // 9) out = relu(bn2(f1))
    apply_bn<<<2048, 1024>>>(f1, out, prm + PO_BN2);
}